// round 6
// baseline (speedup 1.0000x reference)
#include <cuda_runtime.h>
#include <math.h>

// Problem constants
#define BATCH 8
#define SEQ   2048
#define DMODEL 512

// Tiling for SGEMM
#define BM 128
#define BN 128
#define BK 16
#define TM 8
#define TN 8
// threads = (BM/TM)*(BN/TN) = 256

// Scratch in device globals (allocation inside kernel_launch is forbidden).
__device__ float g_Q[BATCH * SEQ * DMODEL];              // 32 MB
__device__ float g_K[BATCH * SEQ * DMODEL];              // 32 MB
__device__ float g_V[BATCH * SEQ * DMODEL];              // 32 MB
__device__ float g_S[(size_t)BATCH * SEQ * SEQ];         // 134 MB (scores / softmax in-place)

// ---------------------------------------------------------------------------
// Generic tiled SGEMM with software-pipelined global loads:
//   TRANSB == false:  C[M,N] = alpha * A[M,K] (row-major) * B[K,N] (row-major)
//   TRANSB == true :  C[M,N] = alpha * A[M,K] (row-major) * B[N,K]^T (row-major)
// Batched over blockIdx.z; per-z A/B/C base pointers come from small arrays so
// the same kernel serves the fused-QKV launch (shared A, 3 different B/C) and
// the batched attention GEMMs (strided A/B/C).
// Requires M % BM == 0, N % BN == 0, K % BK == 0 (holds for all our shapes).
// ---------------------------------------------------------------------------
template <bool TRANSB>
__global__ __launch_bounds__(256) void sgemm_kernel(
    const float* __restrict__ Aall, const float* __restrict__ Ball,
    float* __restrict__ Call,
    int M, int N, int K,
    long sA, long sB, long sC, float alpha)
{
    const float* A = Aall + (long)blockIdx.z * sA;
    const float* B = Ball + (long)blockIdx.z * sB;
    float*       C = Call + (long)blockIdx.z * sC;

    __shared__ float As[BK][BM];
    __shared__ float Bs[BK][BN];

    const int tid = threadIdx.x;
    const int tx  = tid & 15;   // 0..15 -> N direction
    const int ty  = tid >> 4;   // 0..15 -> M direction
    const int rowBlock = blockIdx.y * BM;
    const int colBlock = blockIdx.x * BN;

    // Per-thread global-load addresses (invariant except k0 advance).
    // A tile: 512 float4 loads, 2 per thread.
    const int fA0 = tid, fA1 = tid + 256;
    const int rA0 = fA0 >> 2, kA0 = (fA0 & 3) << 2;
    const int rA1 = fA1 >> 2, kA1 = (fA1 & 3) << 2;

    float acc[TM][TN];
#pragma unroll
    for (int i = 0; i < TM; i++)
#pragma unroll
        for (int j = 0; j < TN; j++) acc[i][j] = 0.0f;

    // ---- prologue: load first tile into registers ----
    float4 pa0, pa1, pb0, pb1;
    {
        pa0 = *(const float4*)(A + (long)(rowBlock + rA0) * K + kA0);
        pa1 = *(const float4*)(A + (long)(rowBlock + rA1) * K + kA1);
        if (!TRANSB) {
            int r0 = fA0 >> 5, c0 = (fA0 & 31) << 2;
            int r1 = fA1 >> 5, c1 = (fA1 & 31) << 2;
            pb0 = *(const float4*)(B + (long)r0 * N + colBlock + c0);
            pb1 = *(const float4*)(B + (long)r1 * N + colBlock + c1);
        } else {
            pb0 = *(const float4*)(B + (long)(colBlock + rA0) * K + kA0);
            pb1 = *(const float4*)(B + (long)(colBlock + rA1) * K + kA1);
        }
    }

    for (int k0 = 0; k0 < K; k0 += BK) {
        // ---- store prefetched tile to smem ----
        As[kA0 + 0][rA0] = pa0.x; As[kA0 + 1][rA0] = pa0.y;
        As[kA0 + 2][rA0] = pa0.z; As[kA0 + 3][rA0] = pa0.w;
        As[kA1 + 0][rA1] = pa1.x; As[kA1 + 1][rA1] = pa1.y;
        As[kA1 + 2][rA1] = pa1.z; As[kA1 + 3][rA1] = pa1.w;
        if (!TRANSB) {
            int r0 = fA0 >> 5, c0 = (fA0 & 31) << 2;
            int r1 = fA1 >> 5, c1 = (fA1 & 31) << 2;
            *(float4*)&Bs[r0][c0] = pb0;
            *(float4*)&Bs[r1][c1] = pb1;
        } else {
            Bs[kA0 + 0][rA0] = pb0.x; Bs[kA0 + 1][rA0] = pb0.y;
            Bs[kA0 + 2][rA0] = pb0.z; Bs[kA0 + 3][rA0] = pb0.w;
            Bs[kA1 + 0][rA1] = pb1.x; Bs[kA1 + 1][rA1] = pb1.y;
            Bs[kA1 + 2][rA1] = pb1.z; Bs[kA1 + 3][rA1] = pb1.w;
        }
        __syncthreads();

        // ---- issue next tile's global loads (latency hidden by FMA block) ----
        const int kn = k0 + BK;
        if (kn < K) {
            pa0 = *(const float4*)(A + (long)(rowBlock + rA0) * K + kn + kA0);
            pa1 = *(const float4*)(A + (long)(rowBlock + rA1) * K + kn + kA1);
            if (!TRANSB) {
                int r0 = fA0 >> 5, c0 = (fA0 & 31) << 2;
                int r1 = fA1 >> 5, c1 = (fA1 & 31) << 2;
                pb0 = *(const float4*)(B + (long)(kn + r0) * N + colBlock + c0);
                pb1 = *(const float4*)(B + (long)(kn + r1) * N + colBlock + c1);
            } else {
                pb0 = *(const float4*)(B + (long)(colBlock + rA0) * K + kn + kA0);
                pb1 = *(const float4*)(B + (long)(colBlock + rA1) * K + kn + kA1);
            }
        }

        // ---- compute on the smem tile ----
#pragma unroll
        for (int k = 0; k < BK; k++) {
            float ra[TM], rb[TN];
            const float4* Ak = (const float4*)(&As[k][ty * TM]);
            const float4* Bk = (const float4*)(&Bs[k][tx * TN]);
            float4 a0 = Ak[0], a1 = Ak[1];
            float4 b0 = Bk[0], b1 = Bk[1];
            ra[0] = a0.x; ra[1] = a0.y; ra[2] = a0.z; ra[3] = a0.w;
            ra[4] = a1.x; ra[5] = a1.y; ra[6] = a1.z; ra[7] = a1.w;
            rb[0] = b0.x; rb[1] = b0.y; rb[2] = b0.z; rb[3] = b0.w;
            rb[4] = b1.x; rb[5] = b1.y; rb[6] = b1.z; rb[7] = b1.w;
#pragma unroll
            for (int i = 0; i < TM; i++)
#pragma unroll
                for (int j = 0; j < TN; j++)
                    acc[i][j] = fmaf(ra[i], rb[j], acc[i][j]);
        }
        __syncthreads();
    }

    // ---- epilogue ----
#pragma unroll
    for (int i = 0; i < TM; i++) {
        long r = rowBlock + ty * TM + i;
#pragma unroll
        for (int j = 0; j < TN; j += 4) {
            float4 v = make_float4(acc[i][j + 0] * alpha,
                                   acc[i][j + 1] * alpha,
                                   acc[i][j + 2] * alpha,
                                   acc[i][j + 3] * alpha);
            *(float4*)(C + r * N + colBlock + tx * TN + j) = v;
        }
    }
}

// ---------------------------------------------------------------------------
// Fused QKV projection: blockIdx.z selects (W, out) among {WQ->Q, WK->K, WV->V}.
// A (= x) is shared by all z. One launch, full-chip wave.
// ---------------------------------------------------------------------------
__global__ __launch_bounds__(256) void qkv_kernel(
    const float* __restrict__ x,
    const float* __restrict__ WQ, const float* __restrict__ WK,
    const float* __restrict__ WV,
    float* __restrict__ Q, float* __restrict__ K_, float* __restrict__ V)
{
    const float* Wsel = (blockIdx.z == 0) ? WQ : (blockIdx.z == 1) ? WK : WV;
    float* Csel       = (blockIdx.z == 0) ? Q  : (blockIdx.z == 1) ? K_ : V;

    const int M = BATCH * SEQ, N = DMODEL, K = DMODEL;
    __shared__ float As[BK][BM];
    __shared__ float Bs[BK][BN];

    const int tid = threadIdx.x;
    const int tx  = tid & 15;
    const int ty  = tid >> 4;
    const int rowBlock = blockIdx.y * BM;
    const int colBlock = blockIdx.x * BN;

    const int fA0 = tid, fA1 = tid + 256;
    const int rA0 = fA0 >> 2, kA0 = (fA0 & 3) << 2;
    const int rA1 = fA1 >> 2, kA1 = (fA1 & 3) << 2;
    const int rB0 = fA0 >> 5, cB0 = (fA0 & 31) << 2;
    const int rB1 = fA1 >> 5, cB1 = (fA1 & 31) << 2;

    float acc[TM][TN];
#pragma unroll
    for (int i = 0; i < TM; i++)
#pragma unroll
        for (int j = 0; j < TN; j++) acc[i][j] = 0.0f;

    float4 pa0 = *(const float4*)(x + (long)(rowBlock + rA0) * K + kA0);
    float4 pa1 = *(const float4*)(x + (long)(rowBlock + rA1) * K + kA1);
    float4 pb0 = *(const float4*)(Wsel + (long)rB0 * N + colBlock + cB0);
    float4 pb1 = *(const float4*)(Wsel + (long)rB1 * N + colBlock + cB1);

    for (int k0 = 0; k0 < K; k0 += BK) {
        As[kA0 + 0][rA0] = pa0.x; As[kA0 + 1][rA0] = pa0.y;
        As[kA0 + 2][rA0] = pa0.z; As[kA0 + 3][rA0] = pa0.w;
        As[kA1 + 0][rA1] = pa1.x; As[kA1 + 1][rA1] = pa1.y;
        As[kA1 + 2][rA1] = pa1.z; As[kA1 + 3][rA1] = pa1.w;
        *(float4*)&Bs[rB0][cB0] = pb0;
        *(float4*)&Bs[rB1][cB1] = pb1;
        __syncthreads();

        const int kn = k0 + BK;
        if (kn < K) {
            pa0 = *(const float4*)(x + (long)(rowBlock + rA0) * K + kn + kA0);
            pa1 = *(const float4*)(x + (long)(rowBlock + rA1) * K + kn + kA1);
            pb0 = *(const float4*)(Wsel + (long)(kn + rB0) * N + colBlock + cB0);
            pb1 = *(const float4*)(Wsel + (long)(kn + rB1) * N + colBlock + cB1);
        }

#pragma unroll
        for (int k = 0; k < BK; k++) {
            float ra[TM], rb[TN];
            const float4* Ak = (const float4*)(&As[k][ty * TM]);
            const float4* Bk = (const float4*)(&Bs[k][tx * TN]);
            float4 a0 = Ak[0], a1 = Ak[1];
            float4 b0 = Bk[0], b1 = Bk[1];
            ra[0] = a0.x; ra[1] = a0.y; ra[2] = a0.z; ra[3] = a0.w;
            ra[4] = a1.x; ra[5] = a1.y; ra[6] = a1.z; ra[7] = a1.w;
            rb[0] = b0.x; rb[1] = b0.y; rb[2] = b0.z; rb[3] = b0.w;
            rb[4] = b1.x; rb[5] = b1.y; rb[6] = b1.z; rb[7] = b1.w;
#pragma unroll
            for (int i = 0; i < TM; i++)
#pragma unroll
                for (int j = 0; j < TN; j++)
                    acc[i][j] = fmaf(ra[i], rb[j], acc[i][j]);
        }
        __syncthreads();
    }

#pragma unroll
    for (int i = 0; i < TM; i++) {
        long r = rowBlock + ty * TM + i;
#pragma unroll
        for (int j = 0; j < TN; j += 4) {
            float4 v = make_float4(acc[i][j + 0], acc[i][j + 1],
                                   acc[i][j + 2], acc[i][j + 3]);
            *(float4*)(Csel + r * N + colBlock + tx * TN + j) = v;
        }
    }
}

// ---------------------------------------------------------------------------
// In-place row softmax over SEQ=2048 columns. One block per row, 256 threads,
// 8 values per thread held in registers (one read + one write of the row).
// ---------------------------------------------------------------------------
__global__ __launch_bounds__(256) void softmax_kernel(float* __restrict__ S)
{
    float* row = S + (size_t)blockIdx.x * SEQ;
    const int tid = threadIdx.x;

    float4 v[2];
    v[0] = *(float4*)(row + tid * 4);
    v[1] = *(float4*)(row + 1024 + tid * 4);

    __shared__ float red[8];

    // ---- max ----
    float m = fmaxf(fmaxf(fmaxf(v[0].x, v[0].y), fmaxf(v[0].z, v[0].w)),
                    fmaxf(fmaxf(v[1].x, v[1].y), fmaxf(v[1].z, v[1].w)));
#pragma unroll
    for (int o = 16; o > 0; o >>= 1) m = fmaxf(m, __shfl_xor_sync(0xffffffffu, m, o));
    if ((tid & 31) == 0) red[tid >> 5] = m;
    __syncthreads();
    if (tid < 8) {
        float t = red[tid];
#pragma unroll
        for (int o = 4; o > 0; o >>= 1) t = fmaxf(t, __shfl_xor_sync(0xffu, t, o));
        if (tid == 0) red[0] = t;
    }
    __syncthreads();
    m = red[0];
    __syncthreads();   // everyone has read red[0] before it's reused

    // ---- exp + sum ----
    float s = 0.0f;
#pragma unroll
    for (int i = 0; i < 2; i++) {
        v[i].x = expf(v[i].x - m); s += v[i].x;
        v[i].y = expf(v[i].y - m); s += v[i].y;
        v[i].z = expf(v[i].z - m); s += v[i].z;
        v[i].w = expf(v[i].w - m); s += v[i].w;
    }
#pragma unroll
    for (int o = 16; o > 0; o >>= 1) s += __shfl_xor_sync(0xffffffffu, s, o);
    if ((tid & 31) == 0) red[tid >> 5] = s;
    __syncthreads();
    if (tid < 8) {
        float t = red[tid];
#pragma unroll
        for (int o = 4; o > 0; o >>= 1) t += __shfl_xor_sync(0xffu, t, o);
        if (tid == 0) red[0] = t;
    }
    __syncthreads();
    const float inv = 1.0f / red[0];

    // ---- normalize + store ----
#pragma unroll
    for (int i = 0; i < 2; i++) {
        v[i].x *= inv; v[i].y *= inv; v[i].z *= inv; v[i].w *= inv;
    }
    *(float4*)(row + tid * 4)        = v[0];
    *(float4*)(row + 1024 + tid * 4) = v[1];
}

// ---------------------------------------------------------------------------
extern "C" void kernel_launch(void* const* d_in, const int* in_sizes, int n_in,
                              void* d_out, int out_size)
{
    (void)in_sizes; (void)n_in; (void)out_size;
    const float* x  = (const float*)d_in[0];   // [8, 2048, 512]
    const float* WQ = (const float*)d_in[1];   // [512, 512]
    const float* WK = (const float*)d_in[2];
    const float* WV = (const float*)d_in[3];
    float* out = (float*)d_out;                // [8, 2048, 512]

    float *Q, *K, *V, *S;
    cudaGetSymbolAddress((void**)&Q, g_Q);
    cudaGetSymbolAddress((void**)&K, g_K);
    cudaGetSymbolAddress((void**)&V, g_V);
    cudaGetSymbolAddress((void**)&S, g_S);

    const int  M  = BATCH * SEQ;                 // 16384
    const long sQKV = (long)SEQ * DMODEL;        // 2048*512
    const long sS   = (long)SEQ * SEQ;           // 2048*2048
    const float scale = 1.0f / sqrtf((float)DMODEL);

    // 1) Fused QKV projections: one launch, z in {Q, K, V}
    {
        dim3 grid(DMODEL / BN, M / BM, 3);       // (4, 128, 3)
        qkv_kernel<<<grid, 256>>>(x, WQ, WK, WV, Q, K, V);
    }

    // 2) Scores: S_b = (Q_b @ K_b^T) * scale   [2048,2048] per batch
    {
        dim3 grid(SEQ / BN, SEQ / BM, BATCH);    // (16, 16, 8)
        sgemm_kernel<true><<<grid, 256>>>(Q, K, S, SEQ, SEQ, DMODEL,
                                          sQKV, sQKV, sS, scale);
    }

    // 3) Row softmax in place on S
    softmax_kernel<<<BATCH * SEQ, 256>>>(S);

    // 4) Output: out_b = W_b @ V_b   [2048,512] per batch
    {
        dim3 grid(DMODEL / BN, SEQ / BM, BATCH); // (4, 16, 8)
        sgemm_kernel<false><<<grid, 256>>>(S, V, out, SEQ, DMODEL, SEQ,
                                           sS, sQKV, sQKV, 1.0f);
    }
}

// round 9
// speedup vs baseline: 1.6431x; 1.6431x over previous
#include <cuda_runtime.h>
#include <cuda_bf16.h>
#include <stdint.h>
#include <math.h>

// ============================================================================
// Problem constants
// ============================================================================
#define BATCH 8
#define SEQ   2048
#define DM    512
#define MTOT  (BATCH * SEQ)   // 16384

// ============================================================================
// Device global scratch (bf16 hi/lo pairs + fp32 scores)
// ============================================================================
__device__ __nv_bfloat16 g_xh[MTOT * DM],  g_xl[MTOT * DM];
__device__ __nv_bfloat16 g_Wth[3][DM * DM], g_Wtl[3][DM * DM];   // transposed W: [n][k]
__device__ __nv_bfloat16 g_Qh[MTOT * DM],  g_Ql[MTOT * DM];
__device__ __nv_bfloat16 g_Kh[MTOT * DM],  g_Kl[MTOT * DM];
__device__ __nv_bfloat16 g_Vth[MTOT * DM], g_Vtl[MTOT * DM];     // transposed V: [b][d][s]
__device__ float         g_S [(size_t)BATCH * SEQ * SEQ];
__device__ __nv_bfloat16 g_Ph[(size_t)BATCH * SEQ * SEQ];
__device__ __nv_bfloat16 g_Pl[(size_t)BATCH * SEQ * SEQ];

// ============================================================================
// PTX helpers (sm_80-level: ldmatrix / mma.sync / cp.async — no 'a' features)
// ============================================================================
__device__ __forceinline__ uint32_t smem_to_u32(const void* p) {
    uint32_t a;
    asm("{ .reg .u64 t; cvta.to.shared.u64 t, %1; cvt.u32.u64 %0, t; }"
        : "=r"(a) : "l"(p));
    return a;
}

__device__ __forceinline__ void cp_async16(uint32_t dst, const void* src) {
    asm volatile("cp.async.cg.shared.global [%0], [%1], 16;"
                 :: "r"(dst), "l"(__cvta_generic_to_global(src)));
}
#define CP_COMMIT() asm volatile("cp.async.commit_group;" ::: "memory")
#define CP_WAIT(n)  asm volatile("cp.async.wait_group %0;" :: "n"(n) : "memory")

__device__ __forceinline__ void ldsm4(uint32_t* r, uint32_t addr) {
    asm volatile("ldmatrix.sync.aligned.m8n8.x4.shared.b16 {%0,%1,%2,%3}, [%4];"
                 : "=r"(r[0]), "=r"(r[1]), "=r"(r[2]), "=r"(r[3]) : "r"(addr));
}

__device__ __forceinline__ void mma_bf16(float* c, const uint32_t* a,
                                         uint32_t b0, uint32_t b1) {
    asm volatile(
        "mma.sync.aligned.m16n8k16.row.col.f32.bf16.bf16.f32 "
        "{%0,%1,%2,%3}, {%4,%5,%6,%7}, {%8,%9}, {%0,%1,%2,%3};"
        : "+f"(c[0]), "+f"(c[1]), "+f"(c[2]), "+f"(c[3])
        : "r"(a[0]), "r"(a[1]), "r"(a[2]), "r"(a[3]), "r"(b0), "r"(b1));
}

__device__ __forceinline__ void split_f32(float v, __nv_bfloat16& h, __nv_bfloat16& l) {
    h = __float2bfloat16(v);
    l = __float2bfloat16(v - __bfloat162float(h));
}

// ============================================================================
// SMEM layout: 4 tiles (Ah, Al, Bh, Bl) per stage, 2 stages.
// Tile = 128 rows x 32 bf16, rows padded to 80 B (conflict-free for ldmatrix).
// ============================================================================
#define PADB      80
#define TILE_SM   (128 * PADB)        // 10240 B
#define STAGE_SM  (4 * TILE_SM)       // 40960 B
#define SMEM_TOTAL (2 * STAGE_SM)     // 81920 B

// ============================================================================
// Core 128x128 GEMM tile body: C = A * B^T  (A[M][K], B[N][K], K-contiguous),
// 3-term bf16 split on mma.sync tensor cores.
//   EPI 0: write bf16 hi/lo row-major (out0/out1, ldC)
//   EPI 1: write bf16 hi/lo transposed (Vt[b][n][s]; batch derived from m row)
//   EPI 2: write fp32 row-major scaled by alpha
// ============================================================================
template <int EPI>
__device__ __forceinline__ void gemm_body(
    const __nv_bfloat16* __restrict__ Ah, const __nv_bfloat16* __restrict__ Al,
    const __nv_bfloat16* __restrict__ Bh, const __nv_bfloat16* __restrict__ Bl,
    void* out0, void* out1, int K, long ldA, long ldB, int ldC, float alpha)
{
    extern __shared__ char smem[];
    const uint32_t sb = smem_to_u32(smem);
    const int tid  = threadIdx.x;
    const int wid  = tid >> 5;
    const int lane = tid & 31;
    const int rowBlock = blockIdx.y * 128;
    const int colBlock = blockIdx.x * 128;
    const int wm = (wid >> 2) * 64;   // warp M offset (2 warps in M)
    const int wn = (wid & 3) * 32;    // warp N offset (4 warps in N)

    float acc[4][4][4];
#pragma unroll
    for (int mt = 0; mt < 4; mt++)
#pragma unroll
        for (int nt = 0; nt < 4; nt++)
#pragma unroll
            for (int e = 0; e < 4; e++) acc[mt][nt][e] = 0.0f;

    // Per-thread staging indices: 512 16B-chunks per tile, 2 per thread.
    const int r0 = tid >> 2,          c0 = tid & 3;
    const int r1 = (tid + 256) >> 2,  c1 = (tid + 256) & 3;

    const __nv_bfloat16* srcA_h = Ah + (long)rowBlock * ldA;
    const __nv_bfloat16* srcA_l = Al + (long)rowBlock * ldA;
    const __nv_bfloat16* srcB_h = Bh + (long)colBlock * ldB;
    const __nv_bfloat16* srcB_l = Bl + (long)colBlock * ldB;

    auto prefetch = [&](int chunk, int stage) {
        const long k0 = (long)chunk * 32;
        const uint32_t s0 = sb + stage * STAGE_SM;
        cp_async16(s0 + 0 * TILE_SM + r0 * PADB + c0 * 16, srcA_h + (long)r0 * ldA + k0 + c0 * 8);
        cp_async16(s0 + 0 * TILE_SM + r1 * PADB + c1 * 16, srcA_h + (long)r1 * ldA + k0 + c1 * 8);
        cp_async16(s0 + 1 * TILE_SM + r0 * PADB + c0 * 16, srcA_l + (long)r0 * ldA + k0 + c0 * 8);
        cp_async16(s0 + 1 * TILE_SM + r1 * PADB + c1 * 16, srcA_l + (long)r1 * ldA + k0 + c1 * 8);
        cp_async16(s0 + 2 * TILE_SM + r0 * PADB + c0 * 16, srcB_h + (long)r0 * ldB + k0 + c0 * 8);
        cp_async16(s0 + 2 * TILE_SM + r1 * PADB + c1 * 16, srcB_h + (long)r1 * ldB + k0 + c1 * 8);
        cp_async16(s0 + 3 * TILE_SM + r0 * PADB + c0 * 16, srcB_l + (long)r0 * ldB + k0 + c0 * 8);
        cp_async16(s0 + 3 * TILE_SM + r1 * PADB + c1 * 16, srcB_l + (long)r1 * ldB + k0 + c1 * 8);
        CP_COMMIT();
    };

    const int NIT = K / 32;
    prefetch(0, 0);
    prefetch(1, 1);

    // ldmatrix per-warp address components (within a stage).
    // A x4: lanes 0-15 -> rows m0..15 @ k0; lanes 16-31 -> same rows @ k8.
    const uint32_t aRow  = (uint32_t)(wm + (lane & 15)) * PADB + ((lane >> 4) * 16);
    // B x4: lanes 0-7: n0-7@k0, 8-15: n0-7@k8, 16-23: n8-15@k0, 24-31: n8-15@k8.
    const uint32_t bRow  = (uint32_t)(wn + ((lane >> 4) << 3) + (lane & 7)) * PADB
                         + (((lane >> 3) & 1) * 16);

    for (int i = 0; i < NIT; i++) {
        if (i + 1 < NIT) { CP_WAIT(1); } else { CP_WAIT(0); }
        __syncthreads();

        const uint32_t s0 = sb + (i & 1) * STAGE_SM;
        const uint32_t aBaseH = s0 + 0 * TILE_SM + aRow;
        const uint32_t aBaseL = s0 + 1 * TILE_SM + aRow;
        const uint32_t bBaseH = s0 + 2 * TILE_SM + bRow;
        const uint32_t bBaseL = s0 + 3 * TILE_SM + bRow;

#pragma unroll
        for (int ks = 0; ks < 2; ks++) {
            const uint32_t ko = ks * 32;            // 16 bf16 = 32 B
            uint32_t ah[4][4], al[4][4], bh[2][4], bl[2][4];
#pragma unroll
            for (int mt = 0; mt < 4; mt++) {
                ldsm4(ah[mt], aBaseH + mt * (16 * PADB) + ko);
                ldsm4(al[mt], aBaseL + mt * (16 * PADB) + ko);
            }
#pragma unroll
            for (int np = 0; np < 2; np++) {
                ldsm4(bh[np], bBaseH + np * (16 * PADB) + ko);
                ldsm4(bl[np], bBaseL + np * (16 * PADB) + ko);
            }
#pragma unroll
            for (int mt = 0; mt < 4; mt++) {
#pragma unroll
                for (int np = 0; np < 2; np++) {
                    // ntile 2*np uses b[np][0..1]; ntile 2*np+1 uses b[np][2..3]
                    mma_bf16(acc[mt][2 * np + 0], ah[mt], bh[np][0], bh[np][1]);
                    mma_bf16(acc[mt][2 * np + 1], ah[mt], bh[np][2], bh[np][3]);
                    mma_bf16(acc[mt][2 * np + 0], ah[mt], bl[np][0], bl[np][1]);
                    mma_bf16(acc[mt][2 * np + 1], ah[mt], bl[np][2], bl[np][3]);
                    mma_bf16(acc[mt][2 * np + 0], al[mt], bh[np][0], bh[np][1]);
                    mma_bf16(acc[mt][2 * np + 1], al[mt], bh[np][2], bh[np][3]);
                }
            }
        }
        __syncthreads();
        if (i + 2 < NIT) prefetch(i + 2, i & 1);
    }

    // ------------------------------------------------------------------ epilogue
    const int mBase = rowBlock + wm + (lane >> 2);
    const int nBase = colBlock + wn + 2 * (lane & 3);
#pragma unroll
    for (int mt = 0; mt < 4; mt++) {
#pragma unroll
        for (int nt = 0; nt < 4; nt++) {
            const int m0 = mBase + mt * 16;
            const int n  = nBase + nt * 8;
            const float v00 = acc[mt][nt][0], v01 = acc[mt][nt][1];
            const float v10 = acc[mt][nt][2], v11 = acc[mt][nt][3];

            if (EPI == 2) {
                float* C = (float*)out0;
                *(float2*)(C + (long)m0 * ldC + n)       = make_float2(v00 * alpha, v01 * alpha);
                *(float2*)(C + (long)(m0 + 8) * ldC + n) = make_float2(v10 * alpha, v11 * alpha);
            } else if (EPI == 0) {
                __nv_bfloat16* H = (__nv_bfloat16*)out0;
                __nv_bfloat16* L = (__nv_bfloat16*)out1;
                __nv_bfloat16 h0, l0, h1, l1;
                split_f32(v00, h0, l0); split_f32(v01, h1, l1);
                *(__nv_bfloat162*)(H + (long)m0 * ldC + n) = __nv_bfloat162(h0, h1);
                *(__nv_bfloat162*)(L + (long)m0 * ldC + n) = __nv_bfloat162(l0, l1);
                split_f32(v10, h0, l0); split_f32(v11, h1, l1);
                *(__nv_bfloat162*)(H + (long)(m0 + 8) * ldC + n) = __nv_bfloat162(h0, h1);
                *(__nv_bfloat162*)(L + (long)(m0 + 8) * ldC + n) = __nv_bfloat162(l0, l1);
            } else {  // EPI == 1: transposed store Vt[b][n][s]
                __nv_bfloat16* H = (__nv_bfloat16*)out0;
                __nv_bfloat16* L = (__nv_bfloat16*)out1;
#pragma unroll
                for (int rr = 0; rr < 2; rr++) {
                    const int m = m0 + rr * 8;
                    const int bb = m >> 11;
                    const int s  = m & 2047;
                    const float va = (rr == 0) ? v00 : v10;
                    const float vb = (rr == 0) ? v01 : v11;
                    __nv_bfloat16 h, l;
                    split_f32(va, h, l);
                    H[((long)bb * DM + n) * SEQ + s] = h;
                    L[((long)bb * DM + n) * SEQ + s] = l;
                    split_f32(vb, h, l);
                    H[((long)bb * DM + n + 1) * SEQ + s] = h;
                    L[((long)bb * DM + n + 1) * SEQ + s] = l;
                }
            }
        }
    }
}

// ---------------------------------------------------------------------------
// GEMM kernels
// ---------------------------------------------------------------------------
__global__ __launch_bounds__(256) void tc_gemm_qkv() {
    const int z = blockIdx.z;
    const __nv_bfloat16* Bh = g_Wth[z];
    const __nv_bfloat16* Bl = g_Wtl[z];
    if (z == 2) {
        gemm_body<1>(g_xh, g_xl, Bh, Bl, g_Vth, g_Vtl, DM, DM, DM, 0, 1.0f);
    } else if (z == 1) {
        gemm_body<0>(g_xh, g_xl, Bh, Bl, g_Kh, g_Kl, DM, DM, DM, DM, 1.0f);
    } else {
        gemm_body<0>(g_xh, g_xl, Bh, Bl, g_Qh, g_Ql, DM, DM, DM, DM, 1.0f);
    }
}

__global__ __launch_bounds__(256) void tc_gemm_scores(float alpha) {
    const long z = blockIdx.z;
    const long sQ = (long)SEQ * DM;
    gemm_body<2>(g_Qh + z * sQ, g_Ql + z * sQ, g_Kh + z * sQ, g_Kl + z * sQ,
                 g_S + z * (long)SEQ * SEQ, nullptr, DM, DM, DM, SEQ, alpha);
}

__global__ __launch_bounds__(256) void tc_gemm_pv(float* out) {
    const long z = blockIdx.z;
    gemm_body<2>(g_Ph + z * (long)SEQ * SEQ, g_Pl + z * (long)SEQ * SEQ,
                 g_Vth + z * (long)DM * SEQ, g_Vtl + z * (long)DM * SEQ,
                 out + z * (long)SEQ * DM, nullptr, SEQ, SEQ, SEQ, DM, 1.0f);
}

// ---------------------------------------------------------------------------
// Conversion kernels
// ---------------------------------------------------------------------------
__global__ __launch_bounds__(256) void convert_x_kernel(const float* __restrict__ x) {
    const long i4 = (long)(blockIdx.x * 256 + threadIdx.x) * 4;
    if (i4 >= (long)MTOT * DM) return;
    float4 v = *(const float4*)(x + i4);
    __nv_bfloat16 h0, l0, h1, l1, h2, l2, h3, l3;
    split_f32(v.x, h0, l0); split_f32(v.y, h1, l1);
    split_f32(v.z, h2, l2); split_f32(v.w, h3, l3);
    *(__nv_bfloat162*)(g_xh + i4)     = __nv_bfloat162(h0, h1);
    *(__nv_bfloat162*)(g_xh + i4 + 2) = __nv_bfloat162(h2, h3);
    *(__nv_bfloat162*)(g_xl + i4)     = __nv_bfloat162(l0, l1);
    *(__nv_bfloat162*)(g_xl + i4 + 2) = __nv_bfloat162(l2, l3);
}

__global__ __launch_bounds__(256) void convert_w_kernel(
    const float* __restrict__ WQ, const float* __restrict__ WK,
    const float* __restrict__ WV)
{
    const int idx = blockIdx.x * 256 + threadIdx.x;
    if (idx >= 3 * DM * DM) return;
    const int w = idx / (DM * DM);
    const int rem = idx - w * DM * DM;
    const int k = rem / DM, n = rem % DM;
    const float* src = (w == 0) ? WQ : (w == 1) ? WK : WV;
    __nv_bfloat16 h, l;
    split_f32(src[k * DM + n], h, l);
    g_Wth[w][n * DM + k] = h;      // transposed: [n][k]
    g_Wtl[w][n * DM + k] = l;
}

// ---------------------------------------------------------------------------
// Softmax: fp32 scores row -> bf16 hi/lo probability row
// ---------------------------------------------------------------------------
__global__ __launch_bounds__(256) void softmax_kernel() {
    const size_t rowoff = (size_t)blockIdx.x * SEQ;
    const float* row = g_S + rowoff;
    const int tid = threadIdx.x;

    float4 v[2];
    v[0] = *(const float4*)(row + tid * 4);
    v[1] = *(const float4*)(row + 1024 + tid * 4);

    __shared__ float red[8];

    float m = fmaxf(fmaxf(fmaxf(v[0].x, v[0].y), fmaxf(v[0].z, v[0].w)),
                    fmaxf(fmaxf(v[1].x, v[1].y), fmaxf(v[1].z, v[1].w)));
#pragma unroll
    for (int o = 16; o > 0; o >>= 1) m = fmaxf(m, __shfl_xor_sync(0xffffffffu, m, o));
    if ((tid & 31) == 0) red[tid >> 5] = m;
    __syncthreads();
    if (tid < 8) {
        float t = red[tid];
#pragma unroll
        for (int o = 4; o > 0; o >>= 1) t = fmaxf(t, __shfl_xor_sync(0xffu, t, o));
        if (tid == 0) red[0] = t;
    }
    __syncthreads();
    m = red[0];
    __syncthreads();

    float s = 0.0f;
#pragma unroll
    for (int i = 0; i < 2; i++) {
        v[i].x = expf(v[i].x - m); s += v[i].x;
        v[i].y = expf(v[i].y - m); s += v[i].y;
        v[i].z = expf(v[i].z - m); s += v[i].z;
        v[i].w = expf(v[i].w - m); s += v[i].w;
    }
#pragma unroll
    for (int o = 16; o > 0; o >>= 1) s += __shfl_xor_sync(0xffffffffu, s, o);
    if ((tid & 31) == 0) red[tid >> 5] = s;
    __syncthreads();
    if (tid < 8) {
        float t = red[tid];
#pragma unroll
        for (int o = 4; o > 0; o >>= 1) t += __shfl_xor_sync(0xffu, t, o);
        if (tid == 0) red[0] = t;
    }
    __syncthreads();
    const float inv = 1.0f / red[0];

    __nv_bfloat16* Ph = g_Ph + rowoff;
    __nv_bfloat16* Pl = g_Pl + rowoff;
#pragma unroll
    for (int i = 0; i < 2; i++) {
        const int base = i * 1024 + tid * 4;
        __nv_bfloat16 h0, l0, h1, l1, h2, l2, h3, l3;
        split_f32(v[i].x * inv, h0, l0);
        split_f32(v[i].y * inv, h1, l1);
        split_f32(v[i].z * inv, h2, l2);
        split_f32(v[i].w * inv, h3, l3);
        *(__nv_bfloat162*)(Ph + base)     = __nv_bfloat162(h0, h1);
        *(__nv_bfloat162*)(Ph + base + 2) = __nv_bfloat162(h2, h3);
        *(__nv_bfloat162*)(Pl + base)     = __nv_bfloat162(l0, l1);
        *(__nv_bfloat162*)(Pl + base + 2) = __nv_bfloat162(l2, l3);
    }
}

// ---------------------------------------------------------------------------
extern "C" void kernel_launch(void* const* d_in, const int* in_sizes, int n_in,
                              void* d_out, int out_size)
{
    (void)in_sizes; (void)n_in; (void)out_size;
    const float* x  = (const float*)d_in[0];
    const float* WQ = (const float*)d_in[1];
    const float* WK = (const float*)d_in[2];
    const float* WV = (const float*)d_in[3];
    float* out = (float*)d_out;

    cudaFuncSetAttribute(tc_gemm_qkv,    cudaFuncAttributeMaxDynamicSharedMemorySize, SMEM_TOTAL);
    cudaFuncSetAttribute(tc_gemm_scores, cudaFuncAttributeMaxDynamicSharedMemorySize, SMEM_TOTAL);
    cudaFuncSetAttribute(tc_gemm_pv,     cudaFuncAttributeMaxDynamicSharedMemorySize, SMEM_TOTAL);

    const float scale = 1.0f / sqrtf((float)DM);

    // 1) fp32 -> bf16 hi/lo conversions
    convert_x_kernel<<<(MTOT * DM / 4 + 255) / 256, 256>>>(x);
    convert_w_kernel<<<(3 * DM * DM + 255) / 256, 256>>>(WQ, WK, WV);

    // 2) QKV projections (tensor cores), fused across z
    {
        dim3 grid(DM / 128, MTOT / 128, 3);       // (4, 128, 3)
        tc_gemm_qkv<<<grid, 256, SMEM_TOTAL>>>();
    }

    // 3) Scores = (Q K^T) * scale  (fp32 out)
    {
        dim3 grid(SEQ / 128, SEQ / 128, BATCH);   // (16, 16, 8)
        tc_gemm_scores<<<grid, 256, SMEM_TOTAL>>>(scale);
    }

    // 4) Softmax -> bf16 hi/lo probabilities
    softmax_kernel<<<BATCH * SEQ, 256>>>();

    // 5) Out = P V  (fp32 out)
    {
        dim3 grid(DM / 128, SEQ / 128, BATCH);    // (4, 16, 8)
        tc_gemm_pv<<<grid, 256, SMEM_TOTAL>>>(out);
    }
}

// round 11
// speedup vs baseline: 2.8045x; 1.7068x over previous
#include <cuda_runtime.h>
#include <cuda_bf16.h>
#include <stdint.h>
#include <math.h>

// ============================================================================
// Problem constants
// ============================================================================
#define BATCH 8
#define SEQ   2048
#define DM    512
#define MTOT  (BATCH * SEQ)   // 16384

// ============================================================================
// Device global scratch (bf16 hi/lo pairs + fp32 scores)
// ============================================================================
__device__ __nv_bfloat16 g_xh[MTOT * DM],  g_xl[MTOT * DM];
__device__ __nv_bfloat16 g_Wth[3][DM * DM], g_Wtl[3][DM * DM];   // transposed W: [n][k]
__device__ __nv_bfloat16 g_Qh[MTOT * DM],  g_Ql[MTOT * DM];
__device__ __nv_bfloat16 g_Kh[MTOT * DM],  g_Kl[MTOT * DM];
__device__ __nv_bfloat16 g_Vth[MTOT * DM], g_Vtl[MTOT * DM];     // transposed V: [b][d][s]
__device__ float         g_S [(size_t)BATCH * SEQ * SEQ];
__device__ __nv_bfloat16 g_Ph[(size_t)BATCH * SEQ * SEQ];
__device__ __nv_bfloat16 g_Pl[(size_t)BATCH * SEQ * SEQ];

// ============================================================================
// PTX helpers (sm_80-level: ldmatrix / mma.sync / cp.async — no 'a' features)
// ============================================================================
__device__ __forceinline__ uint32_t smem_to_u32(const void* p) {
    uint32_t a;
    asm("{ .reg .u64 t; cvta.to.shared.u64 t, %1; cvt.u32.u64 %0, t; }"
        : "=r"(a) : "l"(p));
    return a;
}

__device__ __forceinline__ void cp_async16(uint32_t dst, const void* src) {
    asm volatile("cp.async.cg.shared.global [%0], [%1], 16;"
                 :: "r"(dst), "l"(__cvta_generic_to_global(src)));
}
#define CP_COMMIT() asm volatile("cp.async.commit_group;" ::: "memory")
#define CP_WAIT(n)  asm volatile("cp.async.wait_group %0;" :: "n"(n) : "memory")

__device__ __forceinline__ void ldsm4(uint32_t* r, uint32_t addr) {
    asm volatile("ldmatrix.sync.aligned.m8n8.x4.shared.b16 {%0,%1,%2,%3}, [%4];"
                 : "=r"(r[0]), "=r"(r[1]), "=r"(r[2]), "=r"(r[3]) : "r"(addr));
}

__device__ __forceinline__ void mma_bf16(float* c, const uint32_t* a,
                                         uint32_t b0, uint32_t b1) {
    asm volatile(
        "mma.sync.aligned.m16n8k16.row.col.f32.bf16.bf16.f32 "
        "{%0,%1,%2,%3}, {%4,%5,%6,%7}, {%8,%9}, {%0,%1,%2,%3};"
        : "+f"(c[0]), "+f"(c[1]), "+f"(c[2]), "+f"(c[3])
        : "r"(a[0]), "r"(a[1]), "r"(a[2]), "r"(a[3]), "r"(b0), "r"(b1));
}

__device__ __forceinline__ void split_f32(float v, __nv_bfloat16& h, __nv_bfloat16& l) {
    h = __float2bfloat16(v);
    l = __float2bfloat16(v - __bfloat162float(h));
}

// ============================================================================
// SMEM: CTA tile 128(M) x 256(N), BK=32. Per stage: Ah, Al (128x32 each),
// Bh, Bl (256x32 each). Rows padded to 80 B (conflict-free for ldmatrix).
// 3 stages, single __syncthreads per iteration.
// ============================================================================
#define PADB      80
#define TILE_A    (128 * PADB)                 // 10240 B
#define TILE_B    (256 * PADB)                 // 20480 B
#define STAGE_SM  (2 * TILE_A + 2 * TILE_B)    // 61440 B
#define NSTAGE    3
#define SMEM_TOTAL (NSTAGE * STAGE_SM)         // 184320 B

// ============================================================================
// Core GEMM tile body: C = A * B^T  (A[M][K], B[N][K], K-contiguous),
// 3-term bf16 split on mma.sync tensor cores.
// 8 warps: 2(M) x 4(N); warp tile 64x64; per-thread acc[4][8][4].
//   EPI 0: write bf16 hi/lo row-major (out0/out1, ldC)
//   EPI 1: write bf16 hi/lo transposed (Vt[b][n][s]; batch derived from m row)
//   EPI 2: write fp32 row-major scaled by alpha
// ============================================================================
template <int EPI>
__device__ __forceinline__ void gemm_body(
    const __nv_bfloat16* __restrict__ Ah, const __nv_bfloat16* __restrict__ Al,
    const __nv_bfloat16* __restrict__ Bh, const __nv_bfloat16* __restrict__ Bl,
    void* out0, void* out1, int K, long ldA, long ldB, int ldC, float alpha)
{
    extern __shared__ char smem[];
    const uint32_t sb = smem_to_u32(smem);
    const int tid  = threadIdx.x;
    const int wid  = tid >> 5;
    const int lane = tid & 31;
    const int rowBlock = blockIdx.y * 128;
    const int colBlock = blockIdx.x * 256;
    const int wm = (wid >> 2) * 64;   // warp M offset (2 warps in M)
    const int wn = (wid & 3) * 64;    // warp N offset (4 warps in N)

    float acc[4][8][4];
#pragma unroll
    for (int mt = 0; mt < 4; mt++)
#pragma unroll
        for (int nt = 0; nt < 8; nt++)
#pragma unroll
            for (int e = 0; e < 4; e++) acc[mt][nt][e] = 0.0f;

    const __nv_bfloat16* srcA_h = Ah + (long)rowBlock * ldA;
    const __nv_bfloat16* srcA_l = Al + (long)rowBlock * ldA;
    const __nv_bfloat16* srcB_h = Bh + (long)colBlock * ldB;
    const __nv_bfloat16* srcB_l = Bl + (long)colBlock * ldB;

    // Staging: A tiles 512 chunks (2/thread), B tiles 1024 chunks (4/thread).
    auto prefetch = [&](int chunk, int stage) {
        const long k0 = (long)chunk * 32;
        const uint32_t s0 = sb + stage * STAGE_SM;
#pragma unroll
        for (int j = 0; j < 2; j++) {
            const int t = tid + j * 256;
            const int r = t >> 2, c = t & 3;
            cp_async16(s0 + r * PADB + c * 16,          srcA_h + (long)r * ldA + k0 + c * 8);
            cp_async16(s0 + TILE_A + r * PADB + c * 16, srcA_l + (long)r * ldA + k0 + c * 8);
        }
#pragma unroll
        for (int j = 0; j < 4; j++) {
            const int t = tid + j * 256;
            const int r = t >> 2, c = t & 3;
            cp_async16(s0 + 2 * TILE_A + r * PADB + c * 16,
                       srcB_h + (long)r * ldB + k0 + c * 8);
            cp_async16(s0 + 2 * TILE_A + TILE_B + r * PADB + c * 16,
                       srcB_l + (long)r * ldB + k0 + c * 8);
        }
        CP_COMMIT();
    };

    const int NIT = K / 32;
    prefetch(0, 0);
    prefetch(1, 1);

    // ldmatrix address components within a stage.
    // A x4: lanes 0-15 -> rows m0..15 @ k0; lanes 16-31 -> same rows @ k8.
    const uint32_t aRow = (uint32_t)(wm + (lane & 15)) * PADB + ((lane >> 4) * 16);
    // B x4: lanes 0-7: n0-7@k0, 8-15: n0-7@k8, 16-23: n8-15@k0, 24-31: n8-15@k8.
    const uint32_t bRow = (uint32_t)(wn + ((lane >> 4) << 3) + (lane & 7)) * PADB
                        + (((lane >> 3) & 1) * 16);

    int stage = 0;       // stage holding chunk i
    int pstage = 2;      // stage to receive chunk i+2 (== (i+2)%3)
    for (int i = 0; i < NIT; i++) {
        if (i + 1 < NIT) { CP_WAIT(1); } else { CP_WAIT(0); }
        __syncthreads();

        const uint32_t s0 = sb + stage * STAGE_SM;
        const uint32_t aBaseH = s0 + aRow;
        const uint32_t aBaseL = s0 + TILE_A + aRow;
        const uint32_t bBaseH = s0 + 2 * TILE_A + bRow;
        const uint32_t bBaseL = s0 + 2 * TILE_A + TILE_B + bRow;

#pragma unroll
        for (int ks = 0; ks < 2; ks++) {
            const uint32_t ko = ks * 32;            // 16 bf16 = 32 B
            uint32_t ah[4][4], al[4][4], bh[4][4], bl[4][4];
#pragma unroll
            for (int mt = 0; mt < 4; mt++) {
                ldsm4(ah[mt], aBaseH + mt * (16 * PADB) + ko);
                ldsm4(al[mt], aBaseL + mt * (16 * PADB) + ko);
            }
#pragma unroll
            for (int np = 0; np < 4; np++) {
                ldsm4(bh[np], bBaseH + np * (16 * PADB) + ko);
                ldsm4(bl[np], bBaseL + np * (16 * PADB) + ko);
            }
#pragma unroll
            for (int mt = 0; mt < 4; mt++) {
#pragma unroll
                for (int np = 0; np < 4; np++) {
                    mma_bf16(acc[mt][2 * np + 0], ah[mt], bh[np][0], bh[np][1]);
                    mma_bf16(acc[mt][2 * np + 1], ah[mt], bh[np][2], bh[np][3]);
                    mma_bf16(acc[mt][2 * np + 0], ah[mt], bl[np][0], bl[np][1]);
                    mma_bf16(acc[mt][2 * np + 1], ah[mt], bl[np][2], bl[np][3]);
                    mma_bf16(acc[mt][2 * np + 0], al[mt], bh[np][0], bh[np][1]);
                    mma_bf16(acc[mt][2 * np + 1], al[mt], bh[np][2], bh[np][3]);
                }
            }
        }

        // Chunk i+2 goes into stage (i+2)%3 — last read at iter i-1, so the
        // barrier at the top of THIS iteration made it safe to overwrite.
        if (i + 2 < NIT) prefetch(i + 2, pstage);
        stage  = (stage  == NSTAGE - 1) ? 0 : stage + 1;
        pstage = (pstage == NSTAGE - 1) ? 0 : pstage + 1;
    }

    // ------------------------------------------------------------------ epilogue
    const int mBase = rowBlock + wm + (lane >> 2);
    const int nBase = colBlock + wn + 2 * (lane & 3);
#pragma unroll
    for (int mt = 0; mt < 4; mt++) {
#pragma unroll
        for (int nt = 0; nt < 8; nt++) {
            const int m0 = mBase + mt * 16;
            const int n  = nBase + nt * 8;
            const float v00 = acc[mt][nt][0], v01 = acc[mt][nt][1];
            const float v10 = acc[mt][nt][2], v11 = acc[mt][nt][3];

            if (EPI == 2) {
                float* C = (float*)out0;
                *(float2*)(C + (long)m0 * ldC + n)       = make_float2(v00 * alpha, v01 * alpha);
                *(float2*)(C + (long)(m0 + 8) * ldC + n) = make_float2(v10 * alpha, v11 * alpha);
            } else if (EPI == 0) {
                __nv_bfloat16* H = (__nv_bfloat16*)out0;
                __nv_bfloat16* L = (__nv_bfloat16*)out1;
                __nv_bfloat16 h0, l0, h1, l1;
                split_f32(v00, h0, l0); split_f32(v01, h1, l1);
                *(__nv_bfloat162*)(H + (long)m0 * ldC + n) = __nv_bfloat162(h0, h1);
                *(__nv_bfloat162*)(L + (long)m0 * ldC + n) = __nv_bfloat162(l0, l1);
                split_f32(v10, h0, l0); split_f32(v11, h1, l1);
                *(__nv_bfloat162*)(H + (long)(m0 + 8) * ldC + n) = __nv_bfloat162(h0, h1);
                *(__nv_bfloat162*)(L + (long)(m0 + 8) * ldC + n) = __nv_bfloat162(l0, l1);
            } else {  // EPI == 1: transposed store Vt[b][n][s]
                __nv_bfloat16* H = (__nv_bfloat16*)out0;
                __nv_bfloat16* L = (__nv_bfloat16*)out1;
#pragma unroll
                for (int rr = 0; rr < 2; rr++) {
                    const int m = m0 + rr * 8;
                    const int bb = m >> 11;
                    const int s  = m & 2047;
                    const float va = (rr == 0) ? v00 : v10;
                    const float vb = (rr == 0) ? v01 : v11;
                    __nv_bfloat16 h, l;
                    split_f32(va, h, l);
                    H[((long)bb * DM + n) * SEQ + s] = h;
                    L[((long)bb * DM + n) * SEQ + s] = l;
                    split_f32(vb, h, l);
                    H[((long)bb * DM + n + 1) * SEQ + s] = h;
                    L[((long)bb * DM + n + 1) * SEQ + s] = l;
                }
            }
        }
    }
}

// ---------------------------------------------------------------------------
// GEMM kernels
// ---------------------------------------------------------------------------
__global__ __launch_bounds__(256, 1) void tc_gemm_qkv() {
    const int z = blockIdx.z;
    const __nv_bfloat16* Bh = g_Wth[z];
    const __nv_bfloat16* Bl = g_Wtl[z];
    if (z == 2) {
        gemm_body<1>(g_xh, g_xl, Bh, Bl, g_Vth, g_Vtl, DM, DM, DM, 0, 1.0f);
    } else if (z == 1) {
        gemm_body<0>(g_xh, g_xl, Bh, Bl, g_Kh, g_Kl, DM, DM, DM, DM, 1.0f);
    } else {
        gemm_body<0>(g_xh, g_xl, Bh, Bl, g_Qh, g_Ql, DM, DM, DM, DM, 1.0f);
    }
}

__global__ __launch_bounds__(256, 1) void tc_gemm_scores(float alpha) {
    const long z = blockIdx.z;
    const long sQ = (long)SEQ * DM;
    gemm_body<2>(g_Qh + z * sQ, g_Ql + z * sQ, g_Kh + z * sQ, g_Kl + z * sQ,
                 g_S + z * (long)SEQ * SEQ, nullptr, DM, DM, DM, SEQ, alpha);
}

__global__ __launch_bounds__(256, 1) void tc_gemm_pv(float* out) {
    const long z = blockIdx.z;
    gemm_body<2>(g_Ph + z * (long)SEQ * SEQ, g_Pl + z * (long)SEQ * SEQ,
                 g_Vth + z * (long)DM * SEQ, g_Vtl + z * (long)DM * SEQ,
                 out + z * (long)SEQ * DM, nullptr, SEQ, SEQ, SEQ, DM, 1.0f);
}

// ---------------------------------------------------------------------------
// Conversion kernels
// ---------------------------------------------------------------------------
__global__ __launch_bounds__(256) void convert_x_kernel(const float* __restrict__ x) {
    const long i4 = (long)(blockIdx.x * 256 + threadIdx.x) * 4;
    if (i4 >= (long)MTOT * DM) return;
    float4 v = *(const float4*)(x + i4);
    __nv_bfloat16 h0, l0, h1, l1, h2, l2, h3, l3;
    split_f32(v.x, h0, l0); split_f32(v.y, h1, l1);
    split_f32(v.z, h2, l2); split_f32(v.w, h3, l3);
    *(__nv_bfloat162*)(g_xh + i4)     = __nv_bfloat162(h0, h1);
    *(__nv_bfloat162*)(g_xh + i4 + 2) = __nv_bfloat162(h2, h3);
    *(__nv_bfloat162*)(g_xl + i4)     = __nv_bfloat162(l0, l1);
    *(__nv_bfloat162*)(g_xl + i4 + 2) = __nv_bfloat162(l2, l3);
}

__global__ __launch_bounds__(256) void convert_w_kernel(
    const float* __restrict__ WQ, const float* __restrict__ WK,
    const float* __restrict__ WV)
{
    const int idx = blockIdx.x * 256 + threadIdx.x;
    if (idx >= 3 * DM * DM) return;
    const int w = idx / (DM * DM);
    const int rem = idx - w * DM * DM;
    const int k = rem / DM, n = rem % DM;
    const float* src = (w == 0) ? WQ : (w == 1) ? WK : WV;
    __nv_bfloat16 h, l;
    split_f32(src[k * DM + n], h, l);
    g_Wth[w][n * DM + k] = h;      // transposed: [n][k]
    g_Wtl[w][n * DM + k] = l;
}

// ---------------------------------------------------------------------------
// Softmax: fp32 scores row -> bf16 hi/lo probability row
// ---------------------------------------------------------------------------
__global__ __launch_bounds__(256) void softmax_kernel() {
    const size_t rowoff = (size_t)blockIdx.x * SEQ;
    const float* row = g_S + rowoff;
    const int tid = threadIdx.x;

    float4 v[2];
    v[0] = *(const float4*)(row + tid * 4);
    v[1] = *(const float4*)(row + 1024 + tid * 4);

    __shared__ float red[8];

    float m = fmaxf(fmaxf(fmaxf(v[0].x, v[0].y), fmaxf(v[0].z, v[0].w)),
                    fmaxf(fmaxf(v[1].x, v[1].y), fmaxf(v[1].z, v[1].w)));
#pragma unroll
    for (int o = 16; o > 0; o >>= 1) m = fmaxf(m, __shfl_xor_sync(0xffffffffu, m, o));
    if ((tid & 31) == 0) red[tid >> 5] = m;
    __syncthreads();
    if (tid < 8) {
        float t = red[tid];
#pragma unroll
        for (int o = 4; o > 0; o >>= 1) t = fmaxf(t, __shfl_xor_sync(0xffu, t, o));
        if (tid == 0) red[0] = t;
    }
    __syncthreads();
    m = red[0];
    __syncthreads();

    float s = 0.0f;
#pragma unroll
    for (int i = 0; i < 2; i++) {
        v[i].x = expf(v[i].x - m); s += v[i].x;
        v[i].y = expf(v[i].y - m); s += v[i].y;
        v[i].z = expf(v[i].z - m); s += v[i].z;
        v[i].w = expf(v[i].w - m); s += v[i].w;
    }
#pragma unroll
    for (int o = 16; o > 0; o >>= 1) s += __shfl_xor_sync(0xffffffffu, s, o);
    if ((tid & 31) == 0) red[tid >> 5] = s;
    __syncthreads();
    if (tid < 8) {
        float t = red[tid];
#pragma unroll
        for (int o = 4; o > 0; o >>= 1) t += __shfl_xor_sync(0xffu, t, o);
        if (tid == 0) red[0] = t;
    }
    __syncthreads();
    const float inv = 1.0f / red[0];

    __nv_bfloat16* Ph = g_Ph + rowoff;
    __nv_bfloat16* Pl = g_Pl + rowoff;
#pragma unroll
    for (int i = 0; i < 2; i++) {
        const int base = i * 1024 + tid * 4;
        __nv_bfloat16 h0, l0, h1, l1, h2, l2, h3, l3;
        split_f32(v[i].x * inv, h0, l0);
        split_f32(v[i].y * inv, h1, l1);
        split_f32(v[i].z * inv, h2, l2);
        split_f32(v[i].w * inv, h3, l3);
        *(__nv_bfloat162*)(Ph + base)     = __nv_bfloat162(h0, h1);
        *(__nv_bfloat162*)(Ph + base + 2) = __nv_bfloat162(h2, h3);
        *(__nv_bfloat162*)(Pl + base)     = __nv_bfloat162(l0, l1);
        *(__nv_bfloat162*)(Pl + base + 2) = __nv_bfloat162(l2, l3);
    }
}

// ---------------------------------------------------------------------------
extern "C" void kernel_launch(void* const* d_in, const int* in_sizes, int n_in,
                              void* d_out, int out_size)
{
    (void)in_sizes; (void)n_in; (void)out_size;
    const float* x  = (const float*)d_in[0];
    const float* WQ = (const float*)d_in[1];
    const float* WK = (const float*)d_in[2];
    const float* WV = (const float*)d_in[3];
    float* out = (float*)d_out;

    cudaFuncSetAttribute(tc_gemm_qkv,    cudaFuncAttributeMaxDynamicSharedMemorySize, SMEM_TOTAL);
    cudaFuncSetAttribute(tc_gemm_scores, cudaFuncAttributeMaxDynamicSharedMemorySize, SMEM_TOTAL);
    cudaFuncSetAttribute(tc_gemm_pv,     cudaFuncAttributeMaxDynamicSharedMemorySize, SMEM_TOTAL);

    const float scale = 1.0f / sqrtf((float)DM);

    // 1) fp32 -> bf16 hi/lo conversions
    convert_x_kernel<<<(MTOT * DM / 4 + 255) / 256, 256>>>(x);
    convert_w_kernel<<<(3 * DM * DM + 255) / 256, 256>>>(WQ, WK, WV);

    // 2) QKV projections (tensor cores), fused across z
    {
        dim3 grid(DM / 256, MTOT / 128, 3);       // (2, 128, 3)
        tc_gemm_qkv<<<grid, 256, SMEM_TOTAL>>>();
    }

    // 3) Scores = (Q K^T) * scale  (fp32 out)
    {
        dim3 grid(SEQ / 256, SEQ / 128, BATCH);   // (8, 16, 8)
        tc_gemm_scores<<<grid, 256, SMEM_TOTAL>>>(scale);
    }

    // 4) Softmax -> bf16 hi/lo probabilities
    softmax_kernel<<<BATCH * SEQ, 256>>>();

    // 5) Out = P V  (fp32 out)
    {
        dim3 grid(DM / 256, SEQ / 128, BATCH);    // (2, 16, 8)
        tc_gemm_pv<<<grid, 256, SMEM_TOTAL>>>(out);
    }
}